// round 15
// baseline (speedup 1.0000x reference)
#include <cuda_runtime.h>
#include <cuda_fp16.h>
#include <cstdint>

// Problem constants
#define BB 2
#define SS 2048
#define DD 1024
#define HH 16
#define HEADD 64
#define MROWS (BB*SS)                  // 4096
#define OUT_ELEMS ((size_t)BB*SS*DD)   // 4,194,304
#define XSZ ((size_t)MROWS*DD)         // 4M elements
#define WSZ ((size_t)DD*DD)            // 1M elements

// Scratch (device globals; no allocation allowed) — fp16 everywhere.
__device__ __half g_Xh[3*XSZ];
__device__ __half g_Wh[4*WSZ];
__device__ __half g_Wl[4*WSZ];
// Q hi only, K hi/lo, V single fp16
__device__ __half g_Qh[(size_t)BB*HH*SS*HEADD];
__device__ __half g_Kh[(size_t)BB*HH*SS*HEADD];
__device__ __half g_Kl[(size_t)BB*HH*SS*HEADD];
__device__ __half g_Vh[(size_t)BB*HH*SS*HEADD];

// ---------------------------------------------------------------------------
// Helpers (plain sm_103-safe: mma.sync + ldmatrix + cp.async, sm_80 ISA)
// ---------------------------------------------------------------------------
__device__ __forceinline__ uint32_t smem_to_u32(const void* p) {
    uint32_t a;
    asm("{ .reg .u64 t; cvta.to.shared.u64 t, %1; cvt.u32.u64 %0, t; }"
        : "=r"(a) : "l"(p));
    return a;
}
__device__ __forceinline__ void ldsm4(uint32_t* r, uint32_t addr) {
    asm volatile("ldmatrix.sync.aligned.m8n8.x4.shared.b16 {%0,%1,%2,%3}, [%4];"
        : "=r"(r[0]), "=r"(r[1]), "=r"(r[2]), "=r"(r[3]) : "r"(addr));
}
__device__ __forceinline__ void ldsm4t(uint32_t* r, uint32_t addr) {
    asm volatile("ldmatrix.sync.aligned.m8n8.x4.trans.shared.b16 {%0,%1,%2,%3}, [%4];"
        : "=r"(r[0]), "=r"(r[1]), "=r"(r[2]), "=r"(r[3]) : "r"(addr));
}
__device__ __forceinline__ void mma_fp16(float* c, const uint32_t* a, const uint32_t* b) {
    asm volatile(
        "mma.sync.aligned.m16n8k16.row.col.f32.f16.f16.f32 "
        "{%0,%1,%2,%3}, {%4,%5,%6,%7}, {%8,%9}, {%0,%1,%2,%3};"
        : "+f"(c[0]), "+f"(c[1]), "+f"(c[2]), "+f"(c[3])
        : "r"(a[0]), "r"(a[1]), "r"(a[2]), "r"(a[3]), "r"(b[0]), "r"(b[1]));
}
__device__ __forceinline__ uint32_t cvt2h(float lo, float hi) {
    uint32_t d;
    asm("cvt.rn.f16x2.f32 %0, %1, %2;" : "=r"(d) : "f"(hi), "f"(lo));
    return d;
}
__device__ __forceinline__ void unpackh(uint32_t u, float& lo, float& hi) {
    asm("{.reg .f16 l, h; mov.b32 {l, h}, %2; cvt.f32.f16 %0, l; cvt.f32.f16 %1, h;}"
        : "=f"(lo), "=f"(hi) : "r"(u));
}
__device__ __forceinline__ float ex2f(float x) {
    float r; asm("ex2.approx.f32 %0, %1;" : "=f"(r) : "f"(x)); return r;
}
__device__ __forceinline__ void cpasync16(uint32_t saddr, const void* g) {
    asm volatile("cp.async.cg.shared.global [%0], [%1], 16;" :: "r"(saddr), "l"(g));
}
// streaming stores (written-once data: don't pollute L2)
__device__ __forceinline__ void stcs2(float* p, float x, float y) {
    asm volatile("st.global.cs.v2.f32 [%0], {%1,%2};" :: "l"(p), "f"(x), "f"(y) : "memory");
}
__device__ __forceinline__ void stcs4z(float* p) {
    asm volatile("st.global.cs.v4.f32 [%0], {%1,%1,%1,%1};" :: "l"(p), "f"(0.f) : "memory");
}
#define CP_COMMIT asm volatile("cp.async.commit_group;" ::: "memory")
#define CP_WAITG(n) asm volatile("cp.async.wait_group %0;" :: "n"(n) : "memory")

// ---------------------------------------------------------------------------
// Convert all GEMM inputs. X inputs -> hi only; weights -> hi/lo.
// ---------------------------------------------------------------------------
__global__ void cvt_all(const float4* __restrict__ q, const float4* __restrict__ k,
                        const float4* __restrict__ v,
                        const float4* __restrict__ wq, const float4* __restrict__ wk,
                        const float4* __restrict__ wv, const float4* __restrict__ wo)
{
    const int blk = blockIdx.x;
    if (blk < 768) {
        int slot = blk >> 8;
        size_t base = (size_t)(blk & 255) * 4096;
        const float4* src = (slot == 0) ? q : (slot == 1) ? k : v;
        uint2* dh = (uint2*)(g_Xh + slot * XSZ);
#pragma unroll 4
        for (int j = 0; j < 16; j++) {
            size_t off = base + j * 256 + threadIdx.x;
            float4 x = src[off];
            dh[off] = make_uint2(cvt2h(x.x, x.y), cvt2h(x.z, x.w));
        }
    } else {
        int b2 = blk - 768;
        int slot = b2 >> 6;
        size_t base = (size_t)(b2 & 63) * 4096;
        const float4* src = (slot == 0) ? wq : (slot == 1) ? wk : (slot == 2) ? wv : wo;
        uint2* dh = (uint2*)(g_Wh + slot * WSZ);
        uint2* dl = (uint2*)(g_Wl + slot * WSZ);
#pragma unroll 4
        for (int j = 0; j < 16; j++) {
            size_t off = base + j * 256 + threadIdx.x;
            float4 x = src[off];
            uint32_t H0 = cvt2h(x.x, x.y);
            uint32_t H1 = cvt2h(x.z, x.w);
            float h0, h1, h2, h3;
            unpackh(H0, h0, h1);
            unpackh(H1, h2, h3);
            dh[off] = make_uint2(H0, H1);
            dl[off] = make_uint2(cvt2h(x.x - h0, x.y - h1), cvt2h(x.z - h2, x.w - h3));
        }
    }
}

// ---------------------------------------------------------------------------
// Projection GEMM: Y = X @ W^T + bias, fp16 2-pass, fp32 acc.
// 256 threads, CTA tile 128x256, K chunk 64, cp.async double-buffered.
// mode 0: Q hi (scaled); 1: K hi/lo; 2: V fp16; 3: fp32 Yout.
// QKV launch (zf != nullptr, 384 CTAs): also zero-fills the attn-matrix
// upper triangle (10 fully-zero 128x128 tiles per CTA, interleaved across
// the 16 k-chunks) — hides 252MB of stores under the compute-bound GEMM.
// ---------------------------------------------------------------------------
#define PJ_AH 0
#define PJ_BH 16384
#define PJ_BL 49152
#define PJ_STAGE 81920
#define PJ_ZOFF 163840
#define PJ_SMEM 163904
#define PJ_THREADS 256

__global__ void __launch_bounds__(PJ_THREADS, 1)
proj_tc(const float* __restrict__ bias0, const float* __restrict__ bias1,
        const float* __restrict__ bias2, float* __restrict__ Yout,
        float* __restrict__ zf, int base_mode)
{
    extern __shared__ char smem[];
    const uint32_t sbase = smem_to_u32(smem);
    uint32_t* sZ = (uint32_t*)(smem + PJ_ZOFF);
    const int tid = threadIdx.x;
    const int wid = tid >> 5;
    const int lane = tid & 31;
    const int wm = wid & 1;
    const int wn = wid >> 1;
    const int m0 = blockIdx.y * 128;
    const int n0 = blockIdx.x * 256;
    const int z = blockIdx.z;
    const int mode = base_mode + z;
    const int wslot = (mode == 3) ? 3 : z;

    // zero-fill tile table (QKV launch only): 384 CTAs x 10 tiles = 3840
    if (zf && tid < 10) {
        int T = (blockIdx.x + blockIdx.y * 4 + blockIdx.z * 128) * 10 + tid;
        int bhh = T / 120;
        int w = T % 120;
        int qt = 0;
        while (w >= 15 - qt) { w -= 15 - qt; qt++; }
        int ct = qt + 1 + w;
        sZ[tid] = (uint32_t)((bhh * SS + qt * 128) * SS + ct * 128);
    }

    const __half* Xh = g_Xh + (size_t)z * XSZ;
    const __half* Wh = g_Wh + (size_t)wslot * WSZ;
    const __half* Wl = g_Wl + (size_t)wslot * WSZ;
    const float* bias = (mode == 3) ? bias0 : ((z == 0) ? bias0 : (z == 1) ? bias1 : bias2);

    float acc[4][8][4];
#pragma unroll
    for (int i = 0; i < 4; i++)
#pragma unroll
        for (int j = 0; j < 8; j++)
#pragma unroll
            for (int k = 0; k < 4; k++) acc[i][j][k] = 0.f;

    const int aRow = wm * 64 + (lane & 15);
    const int aSel = lane >> 4;
    const int bRow = wn * 64 + (lane & 7) + ((lane >> 4) << 3);
    const int bSel = (lane >> 3) & 1;

    auto issue = [&](int c) {
        const uint32_t sb = sbase + (c & 1) * PJ_STAGE;
        const int k0 = c * 64;
#pragma unroll
        for (int t = 0; t < 4; t++) {
            int i = tid + t * PJ_THREADS;
            int r = i >> 3, u = i & 7;
            int sw = r * 128 + ((u ^ (r & 7)) << 4);
            cpasync16(sb + PJ_AH + sw, Xh + (size_t)(m0 + r) * DD + k0 + u * 8);
        }
#pragma unroll
        for (int t = 0; t < 8; t++) {
            int i = tid + t * PJ_THREADS;
            int r = i >> 3, u = i & 7;
            int sw = r * 128 + ((u ^ (r & 7)) << 4);
            size_t gw = (size_t)(n0 + r) * DD + k0 + u * 8;
            cpasync16(sb + PJ_BH + sw, Wh + gw);
            cpasync16(sb + PJ_BL + sw, Wl + gw);
        }
    };

    issue(0); CP_COMMIT;
    for (int c = 0; c < 16; c++) {
        if (c + 1 < 16) { issue(c + 1); CP_COMMIT; CP_WAITG(1); }
        else CP_WAITG(0);
        __syncthreads();

        // interleaved upper-triangle zero-fill (fire-and-forget streaming)
        if (zf) {
            const uint32_t rofs = (uint32_t)(c * 8 + (tid >> 5)) * SS + (tid & 31) * 4;
#pragma unroll
            for (int j = 0; j < 10; j++)
                stcs4z(zf + sZ[j] + rofs);
        }

        const uint32_t sb = sbase + (c & 1) * PJ_STAGE;
#pragma unroll
        for (int ks = 0; ks < 4; ks++) {
            uint32_t bh[4][4], bl[4][4];
#pragma unroll
            for (int p = 0; p < 4; p++) {
                int row = bRow + p * 16;
                uint32_t addr = sb + PJ_BH + (uint32_t)row * 128
                              + (uint32_t)(((ks * 2 + bSel) ^ (row & 7)) << 4);
                ldsm4(bh[p], addr);
                ldsm4(bl[p], addr + (PJ_BL - PJ_BH));
            }
#pragma unroll
            for (int mf = 0; mf < 4; mf++) {
                int row = aRow + mf * 16;
                uint32_t addr = sb + (uint32_t)row * 128
                              + (uint32_t)(((ks * 2 + aSel) ^ (row & 7)) << 4);
                uint32_t ah[4];
                ldsm4(ah, addr);
#pragma unroll
                for (int nf = 0; nf < 8; nf++) {
                    const int p = nf >> 1, q = (nf & 1) * 2;
                    mma_fp16(acc[mf][nf], ah, &bh[p][q]);
                    mma_fp16(acc[mf][nf], ah, &bl[p][q]);
                }
            }
        }
        __syncthreads();
    }

    // ---- epilogue ----
    if (mode == 3) {
#pragma unroll
        for (int nf = 0; nf < 8; nf++) {
            const int n = n0 + wn * 64 + nf * 8 + (lane & 3) * 2;
            const float bv0 = bias[n], bv1 = bias[n + 1];
#pragma unroll
            for (int mf = 0; mf < 4; mf++) {
                const int m = m0 + wm * 64 + mf * 16 + (lane >> 2);
                float2 v0, v1;
                v0.x = acc[mf][nf][0] + bv0; v0.y = acc[mf][nf][1] + bv1;
                v1.x = acc[mf][nf][2] + bv0; v1.y = acc[mf][nf][3] + bv1;
                *(float2*)&Yout[(size_t)m * DD + n] = v0;
                *(float2*)&Yout[(size_t)(m + 8) * DD + n] = v1;
            }
        }
    } else if (mode == 1) {
#pragma unroll
        for (int nf = 0; nf < 8; nf++) {
            const int n = n0 + wn * 64 + nf * 8 + (lane & 3) * 2;
            const float bv0 = bias[n], bv1 = bias[n + 1];
            const int h = n >> 6, hd = n & 63;
#pragma unroll
            for (int mf = 0; mf < 4; mf++) {
                const int m = m0 + wm * 64 + mf * 16 + (lane >> 2);
                const int b = m >> 11, s = m & 2047;
                float v0x = acc[mf][nf][0] + bv0;
                float v0y = acc[mf][nf][1] + bv1;
                float v1x = acc[mf][nf][2] + bv0;
                float v1y = acc[mf][nf][3] + bv1;
                uint32_t H0 = cvt2h(v0x, v0y);
                uint32_t H1 = cvt2h(v1x, v1y);
                float h0l, h0h, h1l, h1h;
                unpackh(H0, h0l, h0h);
                unpackh(H1, h1l, h1h);
                uint32_t L0 = cvt2h(v0x - h0l, v0y - h0h);
                uint32_t L1 = cvt2h(v1x - h1l, v1y - h1h);
                size_t off = ((size_t)(b * HH + h) * SS + s) * 32 + (hd >> 1);
                ((uint32_t*)g_Kh)[off] = H0;
                ((uint32_t*)g_Kl)[off] = L0;
                ((uint32_t*)g_Kh)[off + 256] = H1;   // row s+8
                ((uint32_t*)g_Kl)[off + 256] = L1;
            }
        }
    } else {
        uint32_t* dst = (mode == 0) ? (uint32_t*)g_Qh : (uint32_t*)g_Vh;
        const float qs = (mode == 0) ? 0.18033688011112042f : 1.0f;  // log2(e)/8
#pragma unroll
        for (int nf = 0; nf < 8; nf++) {
            const int n = n0 + wn * 64 + nf * 8 + (lane & 3) * 2;
            const float bv0 = bias[n], bv1 = bias[n + 1];
            const int h = n >> 6, hd = n & 63;
#pragma unroll
            for (int mf = 0; mf < 4; mf++) {
                const int m = m0 + wm * 64 + mf * 16 + (lane >> 2);
                const int b = m >> 11, s = m & 2047;
                uint32_t U0 = cvt2h((acc[mf][nf][0] + bv0) * qs, (acc[mf][nf][1] + bv1) * qs);
                uint32_t U1 = cvt2h((acc[mf][nf][2] + bv0) * qs, (acc[mf][nf][3] + bv1) * qs);
                size_t off = ((size_t)(b * HH + h) * SS + s) * 32 + (hd >> 1);
                dst[off] = U0;
                dst[off + 256] = U1;   // row s+8
            }
        }
    }
}

// ---------------------------------------------------------------------------
// Two-phase HMMA attention, fp16, low-replication layout (R14).
// CTA = 128 threads (4 warps), 128 q-rows; each warp owns 32 q-rows x 64 keys.
// Phase A: hi-only QK row sums (qt==0: 2-pass).
// Phase B: 2-pass QK, normalize, write P (streaming), O += P V fp16.
// Upper-triangle zero-fill now lives in proj_tc (QKV launch).
// SMEM: Qh 16KB | K 2x16KB | V 2x8KB = 64KB -> 2 CTAs/SM.
// ---------------------------------------------------------------------------
#define AQH 0
#define AK0 16384
#define AV0 49152
#define ATTN_SMEM 65536
#define AT_THREADS 128

__global__ void __launch_bounds__(AT_THREADS, 2) attn_tc(float* __restrict__ d_attn)
{
    extern __shared__ char smem[];
    const uint32_t sbase = smem_to_u32(smem);
    const int bh = blockIdx.x;
    const int qt = (int)gridDim.y - 1 - (int)blockIdx.y;   // big tiles first
    const int tid = threadIdx.x;
    const int wid = tid >> 5;          // 0..3
    const int lane = tid & 31;
    const int g = lane >> 2, t = lane & 3;
    const int qbase = qt * 128;
    const int nkt = 2 * qt + 2;
    const bool phaseA2 = (qt == 0);

    // ---- load Qh tile (128 rows x 128B), swizzled ----
    {
        const uint4* srcH = (const uint4*)g_Qh + ((size_t)bh * SS + qbase) * 8;
#pragma unroll
        for (int j = 0; j < 8; j++) {
            int i = tid + j * AT_THREADS;
            int r = i >> 3, u = i & 7;
            int sw = r * 128 + ((u ^ (r & 7)) << 4);
            *(uint4*)(smem + AQH + sw) = srcH[r * 8 + u];
        }
    }

    const int aRowB = wid * 32 + (lane & 15);     // + mf*16
    const int aSel = lane >> 4;
    const int bRowB = (lane & 7) + ((lane >> 4) << 3);
    const int bSel = (lane >> 3) & 1;
    const int vRowB = (lane & 7) + (((lane >> 3) & 1) << 3);
    const int vSel = lane >> 4;

    const int q00 = qbase + wid * 32 + g;
    const int q01 = q00 + 8;
    const int q10 = q00 + 16;
    const int q11 = q00 + 24;

    auto issueK = [&](int kt, int st, bool withLo) {
        size_t rb = ((size_t)bh * SS + kt * 64) * 8;
        uint32_t sb = sbase + AK0 + st * 16384;
#pragma unroll
        for (int j = 0; j < 4; j++) {
            int i = tid + j * AT_THREADS;
            int r = i >> 3, u = i & 7;
            int sw = r * 128 + ((u ^ (r & 7)) << 4);
            cpasync16(sb + sw, (const uint4*)g_Kh + rb + r * 8 + u);
            if (withLo) cpasync16(sb + 8192 + sw, (const uint4*)g_Kl + rb + r * 8 + u);
        }
    };
    auto issueV = [&](int kt, int st) {
        size_t rb = ((size_t)bh * SS + kt * 64) * 8;
        uint32_t sb = sbase + AV0 + st * 8192;
#pragma unroll
        for (int j = 0; j < 4; j++) {
            int i = tid + j * AT_THREADS;
            int r = i >> 3, u = i & 7;
            int sw = r * 128 + ((u ^ (r & 7)) << 4);
            cpasync16(sb + sw, (const uint4*)g_Vh + rb + r * 8 + u);
        }
    };

    auto computeS = [&](int st, float s[2][8][4], bool twopass) {
        const uint32_t kb = sbase + AK0 + st * 16384;
#pragma unroll
        for (int mf = 0; mf < 2; mf++)
#pragma unroll
            for (int f = 0; f < 8; f++)
#pragma unroll
                for (int k = 0; k < 4; k++) s[mf][f][k] = 0.f;
#pragma unroll
        for (int ks = 0; ks < 4; ks++) {
            uint32_t ah[2][4];
#pragma unroll
            for (int mf = 0; mf < 2; mf++) {
                int row = aRowB + mf * 16;
                uint32_t addrA = sbase + AQH + (uint32_t)row * 128
                               + (uint32_t)((((ks << 1) + aSel) ^ (row & 7)) << 4);
                ldsm4(ah[mf], addrA);
            }
#pragma unroll
            for (int p = 0; p < 4; p++) {
                int row = bRowB + p * 16;
                uint32_t addrB = kb + (uint32_t)row * 128
                               + (uint32_t)((((ks << 1) + bSel) ^ (row & 7)) << 4);
                uint32_t kh[4], kl[4];
                ldsm4(kh, addrB);
                if (twopass) ldsm4(kl, addrB + 8192);
#pragma unroll
                for (int mf = 0; mf < 2; mf++) {
                    mma_fp16(s[mf][2 * p],     ah[mf], &kh[0]);
                    mma_fp16(s[mf][2 * p + 1], ah[mf], &kh[2]);
                    if (twopass) {
                        mma_fp16(s[mf][2 * p],     ah[mf], &kl[0]);
                        mma_fp16(s[mf][2 * p + 1], ah[mf], &kl[2]);
                    }
                }
            }
        }
    };

    // ================= Phase A: row sums =================
    float rs[2][2] = {{0.f, 0.f}, {0.f, 0.f}};
    issueK(0, 0, phaseA2); CP_COMMIT;
    for (int kt = 0; kt < nkt; kt++) {
        if (kt + 1 < nkt) { issueK(kt + 1, (kt + 1) & 1, phaseA2); CP_COMMIT; CP_WAITG(1); }
        else CP_WAITG(0);
        __syncthreads();
        float s[2][8][4];
        computeS(kt & 1, s, phaseA2);
        __syncthreads();   // stage reads done before next overwrite

        const int kcb = kt * 64 + 2 * t;
#pragma unroll
        for (int mf = 0; mf < 2; mf++) {
            const int qa = qbase + wid * 32 + mf * 16;
            const bool full = (kt * 64 + 63) <= qa;
            const int qr0 = qa + g, qr1 = qr0 + 8;
#pragma unroll
            for (int f = 0; f < 8; f++) {
                int kc = kcb + 8 * f;
                float p0 = ex2f(s[mf][f][0]);
                float p1 = ex2f(s[mf][f][1]);
                float p2 = ex2f(s[mf][f][2]);
                float p3 = ex2f(s[mf][f][3]);
                if (!full) {
                    p0 = (kc     <= qr0) ? p0 : 0.f;
                    p1 = (kc + 1 <= qr0) ? p1 : 0.f;
                    p2 = (kc     <= qr1) ? p2 : 0.f;
                    p3 = (kc + 1 <= qr1) ? p3 : 0.f;
                }
                rs[mf][0] += p0 + p1;
                rs[mf][1] += p2 + p3;
            }
        }
    }
#pragma unroll
    for (int mf = 0; mf < 2; mf++)
#pragma unroll
        for (int rr = 0; rr < 2; rr++) {
            rs[mf][rr] += __shfl_xor_sync(0xFFFFFFFFu, rs[mf][rr], 1);
            rs[mf][rr] += __shfl_xor_sync(0xFFFFFFFFu, rs[mf][rr], 2);
        }
    const float inv00 = 1.f / rs[0][0], inv01 = 1.f / rs[0][1];
    const float inv10 = 1.f / rs[1][0], inv11 = 1.f / rs[1][1];

    // ================= Phase B: normalized P store + O accumulate =========
    float o[2][8][4];
#pragma unroll
    for (int mf = 0; mf < 2; mf++)
#pragma unroll
        for (int f = 0; f < 8; f++)
#pragma unroll
            for (int k = 0; k < 4; k++) o[mf][f][k] = 0.f;

    float* attn00 = d_attn + ((size_t)bh * SS + q00) * SS;
    float* attn01 = d_attn + ((size_t)bh * SS + q01) * SS;
    float* attn10 = d_attn + ((size_t)bh * SS + q10) * SS;
    float* attn11 = d_attn + ((size_t)bh * SS + q11) * SS;

    issueK(0, 0, true); issueV(0, 0); CP_COMMIT;
    for (int kt = 0; kt < nkt; kt++) {
        if (kt + 1 < nkt) {
            issueK(kt + 1, (kt + 1) & 1, true); issueV(kt + 1, (kt + 1) & 1);
            CP_COMMIT; CP_WAITG(1);
        } else CP_WAITG(0);
        __syncthreads();

        float s[2][8][4];
        computeS(kt & 1, s, true);   // 2-pass fp16 QK

        const int kcb = kt * 64 + 2 * t;
        uint32_t pa[2][4][4];
#pragma unroll
        for (int mf = 0; mf < 2; mf++) {
            const int qa = qbase + wid * 32 + mf * 16;
            const bool full = (kt * 64 + 63) <= qa;
            const int qr0 = qa + g, qr1 = qr0 + 8;
            const float i0 = (mf == 0) ? inv00 : inv10;
            const float i1 = (mf == 0) ? inv01 : inv11;
            float* a0 = (mf == 0) ? attn00 : attn10;
            float* a1 = (mf == 0) ? attn01 : attn11;
#pragma unroll
            for (int f = 0; f < 8; f++) {
                int kc = kcb + 8 * f;
                float p0 = ex2f(s[mf][f][0]) * i0;
                float p1 = ex2f(s[mf][f][1]) * i0;
                float p2 = ex2f(s[mf][f][2]) * i1;
                float p3 = ex2f(s[mf][f][3]) * i1;
                if (!full) {
                    p0 = (kc     <= qr0) ? p0 : 0.f;
                    p1 = (kc + 1 <= qr0) ? p1 : 0.f;
                    p2 = (kc     <= qr1) ? p2 : 0.f;
                    p3 = (kc + 1 <= qr1) ? p3 : 0.f;
                }
                stcs2(&a0[kc], p0, p1);
                stcs2(&a1[kc], p2, p3);
                int ks = f >> 1, o2 = (f & 1) << 1;
                pa[mf][ks][o2]     = cvt2h(p0, p1);
                pa[mf][ks][o2 + 1] = cvt2h(p2, p3);
            }
        }

        // O += P V (single-pass fp16), V from this stage
        const uint32_t vb = sbase + AV0 + (kt & 1) * 8192;
#pragma unroll
        for (int ks = 0; ks < 4; ks++) {
            int row = vRowB + ks * 16;
#pragma unroll
            for (int p = 0; p < 4; p++) {
                int cu = p * 2 + vSel;
                uint32_t addrV = vb + (uint32_t)row * 128
                               + (uint32_t)((cu ^ (row & 7)) << 4);
                uint32_t vh[4];
                ldsm4t(vh, addrV);
#pragma unroll
                for (int mf = 0; mf < 2; mf++) {
                    mma_fp16(o[mf][2 * p],     pa[mf][ks], &vh[0]);
                    mma_fp16(o[mf][2 * p + 1], pa[mf][ks], &vh[2]);
                }
            }
        }
        __syncthreads();   // stage reads done before next overwrite
    }

    // ---- store O as single fp16 into X slot 0 (for out projection) ----
    const int b = bh >> 4, h = bh & 15;
    uint32_t* xh = (uint32_t*)g_Xh;
#pragma unroll
    for (int mf = 0; mf < 2; mf++) {
        const int qr0 = (mf == 0) ? q00 : q10;
        const int qr1 = qr0 + 8;
        const size_t base0 = (((size_t)b * SS + qr0) * DD + h * 64) >> 1;
        const size_t base1 = (((size_t)b * SS + qr1) * DD + h * 64) >> 1;
#pragma unroll
        for (int f = 0; f < 8; f++) {
            int col = 8 * f + 2 * t;       // even
            xh[base0 + (col >> 1)] = cvt2h(o[mf][f][0], o[mf][f][1]);
            xh[base1 + (col >> 1)] = cvt2h(o[mf][f][2], o[mf][f][3]);
        }
    }
}

// ---------------------------------------------------------------------------
extern "C" void kernel_launch(void* const* d_in, const int* in_sizes, int n_in,
                              void* d_out, int out_size)
{
    const float* queries = (const float*)d_in[0];
    const float* keys    = (const float*)d_in[1];
    const float* values  = (const float*)d_in[2];
    // d_in[3] = attn_mask (bool, causal) — applied analytically
    const float* wq = (const float*)d_in[4];
    const float* bq = (const float*)d_in[5];
    const float* wk = (const float*)d_in[6];
    const float* bk = (const float*)d_in[7];
    const float* wv = (const float*)d_in[8];
    const float* bv = (const float*)d_in[9];
    const float* wo = (const float*)d_in[10];
    const float* bo = (const float*)d_in[11];

    float* out   = (float*)d_out;
    float* attnW = out + OUT_ELEMS;

    cudaFuncSetAttribute(proj_tc, cudaFuncAttributeMaxDynamicSharedMemorySize, PJ_SMEM);
    cudaFuncSetAttribute(attn_tc, cudaFuncAttributeMaxDynamicSharedMemorySize, ATTN_SMEM);

    // 1) convert all inputs (one launch, high-MLP)
    cvt_all<<<1024, 256>>>((const float4*)queries, (const float4*)keys,
                           (const float4*)values,  (const float4*)wq,
                           (const float4*)wk, (const float4*)wv, (const float4*)wo);

    // 2) Q/K/V projections (grid.z = 3) + interleaved attn upper-triangle
    //    zero-fill (hidden under the compute-bound GEMM)
    dim3 gg(DD / 256, MROWS / 128, 3);   // (4, 32, 3) = 384 CTAs
    proj_tc<<<gg, PJ_THREADS, PJ_SMEM>>>(bq, bk, bv, nullptr, attnW, 0);

    // 3) fused attention (low-replication layout), 2 CTAs/SM
    dim3 ga(BB * HH, SS / 128);          // (32, 16) = 512 CTAs
    attn_tc<<<ga, AT_THREADS, ATTN_SMEM>>>(attnW);

    // 4) output projection (reads X slot 0 written by attn_tc), fp16 2-pass
    dim3 go(DD / 256, MROWS / 128, 1);   // (4, 32) = 128 CTAs
    proj_tc<<<go, PJ_THREADS, PJ_SMEM>>>(bo, nullptr, nullptr, out, nullptr, 3);
}

// round 16
// speedup vs baseline: 1.0167x; 1.0167x over previous
#include <cuda_runtime.h>
#include <cuda_fp16.h>
#include <cstdint>

// Problem constants
#define BB 2
#define SS 2048
#define DD 1024
#define HH 16
#define HEADD 64
#define MROWS (BB*SS)                  // 4096
#define OUT_ELEMS ((size_t)BB*SS*DD)   // 4,194,304
#define XSZ ((size_t)MROWS*DD)         // 4M elements
#define WSZ ((size_t)DD*DD)            // 1M elements

// Scratch (device globals; no allocation allowed) — fp16 everywhere.
__device__ __half g_Xh[3*XSZ];
__device__ __half g_Wh[4*WSZ];
__device__ __half g_Wl[4*WSZ];
// Q hi only, K hi/lo, V single fp16
__device__ __half g_Qh[(size_t)BB*HH*SS*HEADD];
__device__ __half g_Kh[(size_t)BB*HH*SS*HEADD];
__device__ __half g_Kl[(size_t)BB*HH*SS*HEADD];
__device__ __half g_Vh[(size_t)BB*HH*SS*HEADD];

// ---------------------------------------------------------------------------
// Helpers (plain sm_103-safe: mma.sync + ldmatrix + cp.async, sm_80 ISA)
// ---------------------------------------------------------------------------
__device__ __forceinline__ uint32_t smem_to_u32(const void* p) {
    uint32_t a;
    asm("{ .reg .u64 t; cvta.to.shared.u64 t, %1; cvt.u32.u64 %0, t; }"
        : "=r"(a) : "l"(p));
    return a;
}
__device__ __forceinline__ void ldsm4(uint32_t* r, uint32_t addr) {
    asm volatile("ldmatrix.sync.aligned.m8n8.x4.shared.b16 {%0,%1,%2,%3}, [%4];"
        : "=r"(r[0]), "=r"(r[1]), "=r"(r[2]), "=r"(r[3]) : "r"(addr));
}
__device__ __forceinline__ void ldsm4t(uint32_t* r, uint32_t addr) {
    asm volatile("ldmatrix.sync.aligned.m8n8.x4.trans.shared.b16 {%0,%1,%2,%3}, [%4];"
        : "=r"(r[0]), "=r"(r[1]), "=r"(r[2]), "=r"(r[3]) : "r"(addr));
}
__device__ __forceinline__ void mma_fp16(float* c, const uint32_t* a, const uint32_t* b) {
    asm volatile(
        "mma.sync.aligned.m16n8k16.row.col.f32.f16.f16.f32 "
        "{%0,%1,%2,%3}, {%4,%5,%6,%7}, {%8,%9}, {%0,%1,%2,%3};"
        : "+f"(c[0]), "+f"(c[1]), "+f"(c[2]), "+f"(c[3])
        : "r"(a[0]), "r"(a[1]), "r"(a[2]), "r"(a[3]), "r"(b[0]), "r"(b[1]));
}
__device__ __forceinline__ uint32_t cvt2h(float lo, float hi) {
    uint32_t d;
    asm("cvt.rn.f16x2.f32 %0, %1, %2;" : "=r"(d) : "f"(hi), "f"(lo));
    return d;
}
__device__ __forceinline__ void unpackh(uint32_t u, float& lo, float& hi) {
    asm("{.reg .f16 l, h; mov.b32 {l, h}, %2; cvt.f32.f16 %0, l; cvt.f32.f16 %1, h;}"
        : "=f"(lo), "=f"(hi) : "r"(u));
}
__device__ __forceinline__ float ex2f(float x) {
    float r; asm("ex2.approx.f32 %0, %1;" : "=f"(r) : "f"(x)); return r;
}
__device__ __forceinline__ void cpasync16(uint32_t saddr, const void* g) {
    asm volatile("cp.async.cg.shared.global [%0], [%1], 16;" :: "r"(saddr), "l"(g));
}
// streaming stores (written-once data: don't pollute L2)
__device__ __forceinline__ void stcs2(float* p, float x, float y) {
    asm volatile("st.global.cs.v2.f32 [%0], {%1,%2};" :: "l"(p), "f"(x), "f"(y) : "memory");
}
__device__ __forceinline__ void stcs4z(float* p) {
    asm volatile("st.global.cs.v4.f32 [%0], {%1,%1,%1,%1};" :: "l"(p), "f"(0.f) : "memory");
}
#define CP_COMMIT asm volatile("cp.async.commit_group;" ::: "memory")
#define CP_WAITG(n) asm volatile("cp.async.wait_group %0;" :: "n"(n) : "memory")

// ---------------------------------------------------------------------------
// Convert all GEMM inputs. X inputs -> hi only; weights -> hi/lo.
// ---------------------------------------------------------------------------
__global__ void cvt_all(const float4* __restrict__ q, const float4* __restrict__ k,
                        const float4* __restrict__ v,
                        const float4* __restrict__ wq, const float4* __restrict__ wk,
                        const float4* __restrict__ wv, const float4* __restrict__ wo)
{
    const int blk = blockIdx.x;
    if (blk < 768) {
        int slot = blk >> 8;
        size_t base = (size_t)(blk & 255) * 4096;
        const float4* src = (slot == 0) ? q : (slot == 1) ? k : v;
        uint2* dh = (uint2*)(g_Xh + slot * XSZ);
#pragma unroll 4
        for (int j = 0; j < 16; j++) {
            size_t off = base + j * 256 + threadIdx.x;
            float4 x = src[off];
            dh[off] = make_uint2(cvt2h(x.x, x.y), cvt2h(x.z, x.w));
        }
    } else {
        int b2 = blk - 768;
        int slot = b2 >> 6;
        size_t base = (size_t)(b2 & 63) * 4096;
        const float4* src = (slot == 0) ? wq : (slot == 1) ? wk : (slot == 2) ? wv : wo;
        uint2* dh = (uint2*)(g_Wh + slot * WSZ);
        uint2* dl = (uint2*)(g_Wl + slot * WSZ);
#pragma unroll 4
        for (int j = 0; j < 16; j++) {
            size_t off = base + j * 256 + threadIdx.x;
            float4 x = src[off];
            uint32_t H0 = cvt2h(x.x, x.y);
            uint32_t H1 = cvt2h(x.z, x.w);
            float h0, h1, h2, h3;
            unpackh(H0, h0, h1);
            unpackh(H1, h2, h3);
            dh[off] = make_uint2(H0, H1);
            dl[off] = make_uint2(cvt2h(x.x - h0, x.y - h1), cvt2h(x.z - h2, x.w - h3));
        }
    }
}

// ---------------------------------------------------------------------------
// Projection GEMM: Y = X @ W^T + bias, fp16, fp32 acc.
// Pass count per mode: Q (0) and V (2) 1-pass (they're stored as single fp16
// anyway — 2nd pass is below their quantization floor); K (1) and out (3)
// 2-pass (K stored hi/lo; out is the direct output path).
// 256 threads, CTA tile 128x256, K chunk 64, cp.async double-buffered.
// ---------------------------------------------------------------------------
#define PJ_AH 0
#define PJ_BH 16384
#define PJ_BL 49152
#define PJ_STAGE 81920
#define PJ_SMEM 163840
#define PJ_THREADS 256

__global__ void __launch_bounds__(PJ_THREADS, 1)
proj_tc(const float* __restrict__ bias0, const float* __restrict__ bias1,
        const float* __restrict__ bias2, float* __restrict__ Yout, int base_mode)
{
    extern __shared__ char smem[];
    const uint32_t sbase = smem_to_u32(smem);
    const int tid = threadIdx.x;
    const int wid = tid >> 5;
    const int lane = tid & 31;
    const int wm = wid & 1;
    const int wn = wid >> 1;
    const int m0 = blockIdx.y * 128;
    const int n0 = blockIdx.x * 256;
    const int z = blockIdx.z;
    const int mode = base_mode + z;
    const int wslot = (mode == 3) ? 3 : z;
    const bool twop = (mode == 1) || (mode == 3);   // 2-pass for K and out

    const __half* Xh = g_Xh + (size_t)z * XSZ;
    const __half* Wh = g_Wh + (size_t)wslot * WSZ;
    const __half* Wl = g_Wl + (size_t)wslot * WSZ;
    const float* bias = (mode == 3) ? bias0 : ((z == 0) ? bias0 : (z == 1) ? bias1 : bias2);

    float acc[4][8][4];
#pragma unroll
    for (int i = 0; i < 4; i++)
#pragma unroll
        for (int j = 0; j < 8; j++)
#pragma unroll
            for (int k = 0; k < 4; k++) acc[i][j][k] = 0.f;

    const int aRow = wm * 64 + (lane & 15);
    const int aSel = lane >> 4;
    const int bRow = wn * 64 + (lane & 7) + ((lane >> 4) << 3);
    const int bSel = (lane >> 3) & 1;

    auto issue = [&](int c) {
        const uint32_t sb = sbase + (c & 1) * PJ_STAGE;
        const int k0 = c * 64;
#pragma unroll
        for (int t = 0; t < 4; t++) {
            int i = tid + t * PJ_THREADS;
            int r = i >> 3, u = i & 7;
            int sw = r * 128 + ((u ^ (r & 7)) << 4);
            cpasync16(sb + PJ_AH + sw, Xh + (size_t)(m0 + r) * DD + k0 + u * 8);
        }
#pragma unroll
        for (int t = 0; t < 8; t++) {
            int i = tid + t * PJ_THREADS;
            int r = i >> 3, u = i & 7;
            int sw = r * 128 + ((u ^ (r & 7)) << 4);
            size_t gw = (size_t)(n0 + r) * DD + k0 + u * 8;
            cpasync16(sb + PJ_BH + sw, Wh + gw);
            if (twop) cpasync16(sb + PJ_BL + sw, Wl + gw);
        }
    };

    issue(0); CP_COMMIT;
    for (int c = 0; c < 16; c++) {
        if (c + 1 < 16) { issue(c + 1); CP_COMMIT; CP_WAITG(1); }
        else CP_WAITG(0);
        __syncthreads();
        const uint32_t sb = sbase + (c & 1) * PJ_STAGE;
#pragma unroll
        for (int ks = 0; ks < 4; ks++) {
            uint32_t bh[4][4], bl[4][4];
#pragma unroll
            for (int p = 0; p < 4; p++) {
                int row = bRow + p * 16;
                uint32_t addr = sb + PJ_BH + (uint32_t)row * 128
                              + (uint32_t)(((ks * 2 + bSel) ^ (row & 7)) << 4);
                ldsm4(bh[p], addr);
                if (twop) ldsm4(bl[p], addr + (PJ_BL - PJ_BH));
            }
#pragma unroll
            for (int mf = 0; mf < 4; mf++) {
                int row = aRow + mf * 16;
                uint32_t addr = sb + (uint32_t)row * 128
                              + (uint32_t)(((ks * 2 + aSel) ^ (row & 7)) << 4);
                uint32_t ah[4];
                ldsm4(ah, addr);
#pragma unroll
                for (int nf = 0; nf < 8; nf++) {
                    const int p = nf >> 1, q = (nf & 1) * 2;
                    mma_fp16(acc[mf][nf], ah, &bh[p][q]);
                    if (twop) mma_fp16(acc[mf][nf], ah, &bl[p][q]);
                }
            }
        }
        __syncthreads();
    }

    // ---- epilogue ----
    if (mode == 3) {
#pragma unroll
        for (int nf = 0; nf < 8; nf++) {
            const int n = n0 + wn * 64 + nf * 8 + (lane & 3) * 2;
            const float bv0 = bias[n], bv1 = bias[n + 1];
#pragma unroll
            for (int mf = 0; mf < 4; mf++) {
                const int m = m0 + wm * 64 + mf * 16 + (lane >> 2);
                float2 v0, v1;
                v0.x = acc[mf][nf][0] + bv0; v0.y = acc[mf][nf][1] + bv1;
                v1.x = acc[mf][nf][2] + bv0; v1.y = acc[mf][nf][3] + bv1;
                *(float2*)&Yout[(size_t)m * DD + n] = v0;
                *(float2*)&Yout[(size_t)(m + 8) * DD + n] = v1;
            }
        }
    } else if (mode == 1) {
#pragma unroll
        for (int nf = 0; nf < 8; nf++) {
            const int n = n0 + wn * 64 + nf * 8 + (lane & 3) * 2;
            const float bv0 = bias[n], bv1 = bias[n + 1];
            const int h = n >> 6, hd = n & 63;
#pragma unroll
            for (int mf = 0; mf < 4; mf++) {
                const int m = m0 + wm * 64 + mf * 16 + (lane >> 2);
                const int b = m >> 11, s = m & 2047;
                float v0x = acc[mf][nf][0] + bv0;
                float v0y = acc[mf][nf][1] + bv1;
                float v1x = acc[mf][nf][2] + bv0;
                float v1y = acc[mf][nf][3] + bv1;
                uint32_t H0 = cvt2h(v0x, v0y);
                uint32_t H1 = cvt2h(v1x, v1y);
                float h0l, h0h, h1l, h1h;
                unpackh(H0, h0l, h0h);
                unpackh(H1, h1l, h1h);
                uint32_t L0 = cvt2h(v0x - h0l, v0y - h0h);
                uint32_t L1 = cvt2h(v1x - h1l, v1y - h1h);
                size_t off = ((size_t)(b * HH + h) * SS + s) * 32 + (hd >> 1);
                ((uint32_t*)g_Kh)[off] = H0;
                ((uint32_t*)g_Kl)[off] = L0;
                ((uint32_t*)g_Kh)[off + 256] = H1;   // row s+8
                ((uint32_t*)g_Kl)[off + 256] = L1;
            }
        }
    } else {
        uint32_t* dst = (mode == 0) ? (uint32_t*)g_Qh : (uint32_t*)g_Vh;
        const float qs = (mode == 0) ? 0.18033688011112042f : 1.0f;  // log2(e)/8
#pragma unroll
        for (int nf = 0; nf < 8; nf++) {
            const int n = n0 + wn * 64 + nf * 8 + (lane & 3) * 2;
            const float bv0 = bias[n], bv1 = bias[n + 1];
            const int h = n >> 6, hd = n & 63;
#pragma unroll
            for (int mf = 0; mf < 4; mf++) {
                const int m = m0 + wm * 64 + mf * 16 + (lane >> 2);
                const int b = m >> 11, s = m & 2047;
                uint32_t U0 = cvt2h((acc[mf][nf][0] + bv0) * qs, (acc[mf][nf][1] + bv1) * qs);
                uint32_t U1 = cvt2h((acc[mf][nf][2] + bv0) * qs, (acc[mf][nf][3] + bv1) * qs);
                size_t off = ((size_t)(b * HH + h) * SS + s) * 32 + (hd >> 1);
                dst[off] = U0;
                dst[off + 256] = U1;   // row s+8
            }
        }
    }
}

// ---------------------------------------------------------------------------
// Two-phase HMMA attention, fp16, low-replication layout (R14, reverted).
// CTA = 128 threads (4 warps), 128 q-rows; each warp owns 32 q-rows x 64 keys.
// Phase A: hi-only QK row sums (qt==0: 2-pass).
// Phase B: 2-pass QK, normalize, write P (streaming), O += P V fp16.
// Zero-fills its upper-triangle strip (streaming stores; overlapped).
// SMEM: Qh 16KB | K 2x16KB | V 2x8KB = 64KB -> 2 CTAs/SM.
// ---------------------------------------------------------------------------
#define AQH 0
#define AK0 16384
#define AV0 49152
#define ATTN_SMEM 65536
#define AT_THREADS 128

__global__ void __launch_bounds__(AT_THREADS, 2) attn_tc(float* __restrict__ d_attn)
{
    extern __shared__ char smem[];
    const uint32_t sbase = smem_to_u32(smem);
    const int bh = blockIdx.x;
    const int qt = (int)gridDim.y - 1 - (int)blockIdx.y;   // big tiles first
    const int tid = threadIdx.x;
    const int wid = tid >> 5;          // 0..3
    const int lane = tid & 31;
    const int g = lane >> 2, t = lane & 3;
    const int qbase = qt * 128;
    const int nkt = 2 * qt + 2;
    const bool phaseA2 = (qt == 0);

    // ---- load Qh tile (128 rows x 128B), swizzled ----
    {
        const uint4* srcH = (const uint4*)g_Qh + ((size_t)bh * SS + qbase) * 8;
#pragma unroll
        for (int j = 0; j < 8; j++) {
            int i = tid + j * AT_THREADS;
            int r = i >> 3, u = i & 7;
            int sw = r * 128 + ((u ^ (r & 7)) << 4);
            *(uint4*)(smem + AQH + sw) = srcH[r * 8 + u];
        }
    }

    const int aRowB = wid * 32 + (lane & 15);     // + mf*16
    const int aSel = lane >> 4;
    const int bRowB = (lane & 7) + ((lane >> 4) << 3);
    const int bSel = (lane >> 3) & 1;
    const int vRowB = (lane & 7) + (((lane >> 3) & 1) << 3);
    const int vSel = lane >> 4;

    const int q00 = qbase + wid * 32 + g;
    const int q01 = q00 + 8;
    const int q10 = q00 + 16;
    const int q11 = q00 + 24;

    auto issueK = [&](int kt, int st, bool withLo) {
        size_t rb = ((size_t)bh * SS + kt * 64) * 8;
        uint32_t sb = sbase + AK0 + st * 16384;
#pragma unroll
        for (int j = 0; j < 4; j++) {
            int i = tid + j * AT_THREADS;
            int r = i >> 3, u = i & 7;
            int sw = r * 128 + ((u ^ (r & 7)) << 4);
            cpasync16(sb + sw, (const uint4*)g_Kh + rb + r * 8 + u);
            if (withLo) cpasync16(sb + 8192 + sw, (const uint4*)g_Kl + rb + r * 8 + u);
        }
    };
    auto issueV = [&](int kt, int st) {
        size_t rb = ((size_t)bh * SS + kt * 64) * 8;
        uint32_t sb = sbase + AV0 + st * 8192;
#pragma unroll
        for (int j = 0; j < 4; j++) {
            int i = tid + j * AT_THREADS;
            int r = i >> 3, u = i & 7;
            int sw = r * 128 + ((u ^ (r & 7)) << 4);
            cpasync16(sb + sw, (const uint4*)g_Vh + rb + r * 8 + u);
        }
    };

    auto computeS = [&](int st, float s[2][8][4], bool twopass) {
        const uint32_t kb = sbase + AK0 + st * 16384;
#pragma unroll
        for (int mf = 0; mf < 2; mf++)
#pragma unroll
            for (int f = 0; f < 8; f++)
#pragma unroll
                for (int k = 0; k < 4; k++) s[mf][f][k] = 0.f;
#pragma unroll
        for (int ks = 0; ks < 4; ks++) {
            uint32_t ah[2][4];
#pragma unroll
            for (int mf = 0; mf < 2; mf++) {
                int row = aRowB + mf * 16;
                uint32_t addrA = sbase + AQH + (uint32_t)row * 128
                               + (uint32_t)((((ks << 1) + aSel) ^ (row & 7)) << 4);
                ldsm4(ah[mf], addrA);
            }
#pragma unroll
            for (int p = 0; p < 4; p++) {
                int row = bRowB + p * 16;
                uint32_t addrB = kb + (uint32_t)row * 128
                               + (uint32_t)((((ks << 1) + bSel) ^ (row & 7)) << 4);
                uint32_t kh[4], kl[4];
                ldsm4(kh, addrB);
                if (twopass) ldsm4(kl, addrB + 8192);
#pragma unroll
                for (int mf = 0; mf < 2; mf++) {
                    mma_fp16(s[mf][2 * p],     ah[mf], &kh[0]);
                    mma_fp16(s[mf][2 * p + 1], ah[mf], &kh[2]);
                    if (twopass) {
                        mma_fp16(s[mf][2 * p],     ah[mf], &kl[0]);
                        mma_fp16(s[mf][2 * p + 1], ah[mf], &kl[2]);
                    }
                }
            }
        }
    };

    // ================= Phase A: row sums =================
    float rs[2][2] = {{0.f, 0.f}, {0.f, 0.f}};
    issueK(0, 0, phaseA2); CP_COMMIT;
    for (int kt = 0; kt < nkt; kt++) {
        if (kt + 1 < nkt) { issueK(kt + 1, (kt + 1) & 1, phaseA2); CP_COMMIT; CP_WAITG(1); }
        else CP_WAITG(0);
        __syncthreads();
        float s[2][8][4];
        computeS(kt & 1, s, phaseA2);
        __syncthreads();   // stage reads done before next overwrite

        const int kcb = kt * 64 + 2 * t;
#pragma unroll
        for (int mf = 0; mf < 2; mf++) {
            const int qa = qbase + wid * 32 + mf * 16;
            const bool full = (kt * 64 + 63) <= qa;
            const int qr0 = qa + g, qr1 = qr0 + 8;
#pragma unroll
            for (int f = 0; f < 8; f++) {
                int kc = kcb + 8 * f;
                float p0 = ex2f(s[mf][f][0]);
                float p1 = ex2f(s[mf][f][1]);
                float p2 = ex2f(s[mf][f][2]);
                float p3 = ex2f(s[mf][f][3]);
                if (!full) {
                    p0 = (kc     <= qr0) ? p0 : 0.f;
                    p1 = (kc + 1 <= qr0) ? p1 : 0.f;
                    p2 = (kc     <= qr1) ? p2 : 0.f;
                    p3 = (kc + 1 <= qr1) ? p3 : 0.f;
                }
                rs[mf][0] += p0 + p1;
                rs[mf][1] += p2 + p3;
            }
        }
    }
#pragma unroll
    for (int mf = 0; mf < 2; mf++)
#pragma unroll
        for (int rr = 0; rr < 2; rr++) {
            rs[mf][rr] += __shfl_xor_sync(0xFFFFFFFFu, rs[mf][rr], 1);
            rs[mf][rr] += __shfl_xor_sync(0xFFFFFFFFu, rs[mf][rr], 2);
        }
    const float inv00 = 1.f / rs[0][0], inv01 = 1.f / rs[0][1];
    const float inv10 = 1.f / rs[1][0], inv11 = 1.f / rs[1][1];

    // ---- zero-fill this CTA's upper-triangle strip (streaming stores) ----
    {
        const int zstart = qbase + 128;
        for (int r = 0; r < 128 && zstart < SS; r++) {
            float* rowp = d_attn + ((size_t)bh * SS + qbase + r) * SS;
            for (int kc = zstart + tid * 4; kc < SS; kc += AT_THREADS * 4)
                stcs4z(&rowp[kc]);
        }
    }

    // ================= Phase B: normalized P store + O accumulate =========
    float o[2][8][4];
#pragma unroll
    for (int mf = 0; mf < 2; mf++)
#pragma unroll
        for (int f = 0; f < 8; f++)
#pragma unroll
            for (int k = 0; k < 4; k++) o[mf][f][k] = 0.f;

    float* attn00 = d_attn + ((size_t)bh * SS + q00) * SS;
    float* attn01 = d_attn + ((size_t)bh * SS + q01) * SS;
    float* attn10 = d_attn + ((size_t)bh * SS + q10) * SS;
    float* attn11 = d_attn + ((size_t)bh * SS + q11) * SS;

    issueK(0, 0, true); issueV(0, 0); CP_COMMIT;
    for (int kt = 0; kt < nkt; kt++) {
        if (kt + 1 < nkt) {
            issueK(kt + 1, (kt + 1) & 1, true); issueV(kt + 1, (kt + 1) & 1);
            CP_COMMIT; CP_WAITG(1);
        } else CP_WAITG(0);
        __syncthreads();

        float s[2][8][4];
        computeS(kt & 1, s, true);   // 2-pass fp16 QK

        const int kcb = kt * 64 + 2 * t;
        uint32_t pa[2][4][4];
#pragma unroll
        for (int mf = 0; mf < 2; mf++) {
            const int qa = qbase + wid * 32 + mf * 16;
            const bool full = (kt * 64 + 63) <= qa;
            const int qr0 = qa + g, qr1 = qr0 + 8;
            const float i0 = (mf == 0) ? inv00 : inv10;
            const float i1 = (mf == 0) ? inv01 : inv11;
            float* a0 = (mf == 0) ? attn00 : attn10;
            float* a1 = (mf == 0) ? attn01 : attn11;
#pragma unroll
            for (int f = 0; f < 8; f++) {
                int kc = kcb + 8 * f;
                float p0 = ex2f(s[mf][f][0]) * i0;
                float p1 = ex2f(s[mf][f][1]) * i0;
                float p2 = ex2f(s[mf][f][2]) * i1;
                float p3 = ex2f(s[mf][f][3]) * i1;
                if (!full) {
                    p0 = (kc     <= qr0) ? p0 : 0.f;
                    p1 = (kc + 1 <= qr0) ? p1 : 0.f;
                    p2 = (kc     <= qr1) ? p2 : 0.f;
                    p3 = (kc + 1 <= qr1) ? p3 : 0.f;
                }
                stcs2(&a0[kc], p0, p1);
                stcs2(&a1[kc], p2, p3);
                int ks = f >> 1, o2 = (f & 1) << 1;
                pa[mf][ks][o2]     = cvt2h(p0, p1);
                pa[mf][ks][o2 + 1] = cvt2h(p2, p3);
            }
        }

        // O += P V (single-pass fp16), V from this stage
        const uint32_t vb = sbase + AV0 + (kt & 1) * 8192;
#pragma unroll
        for (int ks = 0; ks < 4; ks++) {
            int row = vRowB + ks * 16;
#pragma unroll
            for (int p = 0; p < 4; p++) {
                int cu = p * 2 + vSel;
                uint32_t addrV = vb + (uint32_t)row * 128
                               + (uint32_t)((cu ^ (row & 7)) << 4);
                uint32_t vh[4];
                ldsm4t(vh, addrV);
#pragma unroll
                for (int mf = 0; mf < 2; mf++) {
                    mma_fp16(o[mf][2 * p],     pa[mf][ks], &vh[0]);
                    mma_fp16(o[mf][2 * p + 1], pa[mf][ks], &vh[2]);
                }
            }
        }
        __syncthreads();   // stage reads done before next overwrite
    }

    // ---- store O as single fp16 into X slot 0 (for out projection) ----
    const int b = bh >> 4, h = bh & 15;
    uint32_t* xh = (uint32_t*)g_Xh;
#pragma unroll
    for (int mf = 0; mf < 2; mf++) {
        const int qr0 = (mf == 0) ? q00 : q10;
        const int qr1 = qr0 + 8;
        const size_t base0 = (((size_t)b * SS + qr0) * DD + h * 64) >> 1;
        const size_t base1 = (((size_t)b * SS + qr1) * DD + h * 64) >> 1;
#pragma unroll
        for (int f = 0; f < 8; f++) {
            int col = 8 * f + 2 * t;       // even
            xh[base0 + (col >> 1)] = cvt2h(o[mf][f][0], o[mf][f][1]);
            xh[base1 + (col >> 1)] = cvt2h(o[mf][f][2], o[mf][f][3]);
        }
    }
}

// ---------------------------------------------------------------------------
extern "C" void kernel_launch(void* const* d_in, const int* in_sizes, int n_in,
                              void* d_out, int out_size)
{
    const float* queries = (const float*)d_in[0];
    const float* keys    = (const float*)d_in[1];
    const float* values  = (const float*)d_in[2];
    // d_in[3] = attn_mask (bool, causal) — applied analytically
    const float* wq = (const float*)d_in[4];
    const float* bq = (const float*)d_in[5];
    const float* wk = (const float*)d_in[6];
    const float* bk = (const float*)d_in[7];
    const float* wv = (const float*)d_in[8];
    const float* bv = (const float*)d_in[9];
    const float* wo = (const float*)d_in[10];
    const float* bo = (const float*)d_in[11];

    float* out   = (float*)d_out;
    float* attnW = out + OUT_ELEMS;

    cudaFuncSetAttribute(proj_tc, cudaFuncAttributeMaxDynamicSharedMemorySize, PJ_SMEM);
    cudaFuncSetAttribute(attn_tc, cudaFuncAttributeMaxDynamicSharedMemorySize, ATTN_SMEM);

    // 1) convert all inputs (one launch, high-MLP)
    cvt_all<<<1024, 256>>>((const float4*)queries, (const float4*)keys,
                           (const float4*)values,  (const float4*)wq,
                           (const float4*)wk, (const float4*)wv, (const float4*)wo);

    // 2) Q/K/V projections in one launch (grid.z = 3): Q,V 1-pass; K 2-pass
    dim3 gg(DD / 256, MROWS / 128, 3);   // (4, 32, 3) = 384 CTAs
    proj_tc<<<gg, PJ_THREADS, PJ_SMEM>>>(bq, bk, bv, nullptr, 0);

    // 3) fused attention (low-replication layout, own zero-fill), 2 CTAs/SM
    dim3 ga(BB * HH, SS / 128);          // (32, 16) = 512 CTAs
    attn_tc<<<ga, AT_THREADS, ATTN_SMEM>>>(attnW);

    // 4) output projection (reads X slot 0 written by attn_tc), fp16 2-pass
    dim3 go(DD / 256, MROWS / 128, 1);   // (4, 32) = 128 CTAs
    proj_tc<<<go, PJ_THREADS, PJ_SMEM>>>(bo, nullptr, nullptr, out, 3);
}

// round 17
// speedup vs baseline: 1.0991x; 1.0811x over previous
#include <cuda_runtime.h>
#include <cuda_fp16.h>
#include <cstdint>

// Problem constants
#define BB 2
#define SS 2048
#define DD 1024
#define HH 16
#define HEADD 64
#define MROWS (BB*SS)                  // 4096
#define OUT_ELEMS ((size_t)BB*SS*DD)   // 4,194,304
#define XSZ ((size_t)MROWS*DD)         // 4M elements
#define WSZ ((size_t)DD*DD)            // 1M elements

// Scratch (device globals; no allocation allowed) — fp16 everywhere.
__device__ __half g_Xh[3*XSZ];
__device__ __half g_Wh[4*WSZ];
__device__ __half g_Wl[WSZ];           // lo split only for wo (out-proj 2-pass)
// Q, K, V all single fp16 (quantization ~2^-11; measured-safe error budget)
__device__ __half g_Qh[(size_t)BB*HH*SS*HEADD];
__device__ __half g_Kh[(size_t)BB*HH*SS*HEADD];
__device__ __half g_Vh[(size_t)BB*HH*SS*HEADD];

// ---------------------------------------------------------------------------
// Helpers (plain sm_103-safe: mma.sync + ldmatrix + cp.async, sm_80 ISA)
// ---------------------------------------------------------------------------
__device__ __forceinline__ uint32_t smem_to_u32(const void* p) {
    uint32_t a;
    asm("{ .reg .u64 t; cvta.to.shared.u64 t, %1; cvt.u32.u64 %0, t; }"
        : "=r"(a) : "l"(p));
    return a;
}
__device__ __forceinline__ void ldsm4(uint32_t* r, uint32_t addr) {
    asm volatile("ldmatrix.sync.aligned.m8n8.x4.shared.b16 {%0,%1,%2,%3}, [%4];"
        : "=r"(r[0]), "=r"(r[1]), "=r"(r[2]), "=r"(r[3]) : "r"(addr));
}
__device__ __forceinline__ void ldsm4t(uint32_t* r, uint32_t addr) {
    asm volatile("ldmatrix.sync.aligned.m8n8.x4.trans.shared.b16 {%0,%1,%2,%3}, [%4];"
        : "=r"(r[0]), "=r"(r[1]), "=r"(r[2]), "=r"(r[3]) : "r"(addr));
}
__device__ __forceinline__ void mma_fp16(float* c, const uint32_t* a, const uint32_t* b) {
    asm volatile(
        "mma.sync.aligned.m16n8k16.row.col.f32.f16.f16.f32 "
        "{%0,%1,%2,%3}, {%4,%5,%6,%7}, {%8,%9}, {%0,%1,%2,%3};"
        : "+f"(c[0]), "+f"(c[1]), "+f"(c[2]), "+f"(c[3])
        : "r"(a[0]), "r"(a[1]), "r"(a[2]), "r"(a[3]), "r"(b[0]), "r"(b[1]));
}
__device__ __forceinline__ uint32_t cvt2h(float lo, float hi) {
    uint32_t d;
    asm("cvt.rn.f16x2.f32 %0, %1, %2;" : "=r"(d) : "f"(hi), "f"(lo));
    return d;
}
__device__ __forceinline__ void unpackh(uint32_t u, float& lo, float& hi) {
    asm("{.reg .f16 l, h; mov.b32 {l, h}, %2; cvt.f32.f16 %0, l; cvt.f32.f16 %1, h;}"
        : "=f"(lo), "=f"(hi) : "r"(u));
}
__device__ __forceinline__ float ex2f(float x) {
    float r; asm("ex2.approx.f32 %0, %1;" : "=f"(r) : "f"(x)); return r;
}
__device__ __forceinline__ void cpasync16(uint32_t saddr, const void* g) {
    asm volatile("cp.async.cg.shared.global [%0], [%1], 16;" :: "r"(saddr), "l"(g));
}
// streaming stores (written-once data: don't pollute L2)
__device__ __forceinline__ void stcs2(float* p, float x, float y) {
    asm volatile("st.global.cs.v2.f32 [%0], {%1,%2};" :: "l"(p), "f"(x), "f"(y) : "memory");
}
__device__ __forceinline__ void stcs4z(float* p) {
    asm volatile("st.global.cs.v4.f32 [%0], {%1,%1,%1,%1};" :: "l"(p), "f"(0.f) : "memory");
}
#define CP_COMMIT asm volatile("cp.async.commit_group;" ::: "memory")
#define CP_WAITG(n) asm volatile("cp.async.wait_group %0;" :: "n"(n) : "memory")

// ---------------------------------------------------------------------------
// Convert all GEMM inputs. X inputs + wq/wk/wv -> hi only; wo -> hi/lo.
// ---------------------------------------------------------------------------
__global__ void cvt_all(const float4* __restrict__ q, const float4* __restrict__ k,
                        const float4* __restrict__ v,
                        const float4* __restrict__ wq, const float4* __restrict__ wk,
                        const float4* __restrict__ wv, const float4* __restrict__ wo)
{
    const int blk = blockIdx.x;
    if (blk < 768) {
        int slot = blk >> 8;
        size_t base = (size_t)(blk & 255) * 4096;
        const float4* src = (slot == 0) ? q : (slot == 1) ? k : v;
        uint2* dh = (uint2*)(g_Xh + slot * XSZ);
#pragma unroll 4
        for (int j = 0; j < 16; j++) {
            size_t off = base + j * 256 + threadIdx.x;
            float4 x = src[off];
            dh[off] = make_uint2(cvt2h(x.x, x.y), cvt2h(x.z, x.w));
        }
    } else {
        int b2 = blk - 768;
        int slot = b2 >> 6;
        size_t base = (size_t)(b2 & 63) * 4096;
        const float4* src = (slot == 0) ? wq : (slot == 1) ? wk : (slot == 2) ? wv : wo;
        uint2* dh = (uint2*)(g_Wh + slot * WSZ);
        const bool wlo = (slot == 3);
#pragma unroll 4
        for (int j = 0; j < 16; j++) {
            size_t off = base + j * 256 + threadIdx.x;
            float4 x = src[off];
            uint32_t H0 = cvt2h(x.x, x.y);
            uint32_t H1 = cvt2h(x.z, x.w);
            dh[off] = make_uint2(H0, H1);
            if (wlo) {
                float h0, h1, h2, h3;
                unpackh(H0, h0, h1);
                unpackh(H1, h2, h3);
                ((uint2*)g_Wl)[off] =
                    make_uint2(cvt2h(x.x - h0, x.y - h1), cvt2h(x.z - h2, x.w - h3));
            }
        }
    }
}

// ---------------------------------------------------------------------------
// Projection GEMM: Y = X @ W^T + bias, fp16, fp32 acc.
// Modes 0/1/2 (QKV): 1-pass (targets stored as single fp16 anyway).
// Mode 3 (out): 2-pass (Xh*Wh + Xh*Wl) — direct output path.
// 256 threads, CTA tile 128x256, K chunk 64, cp.async double-buffered.
// ---------------------------------------------------------------------------
#define PJ_AH 0
#define PJ_BH 16384
#define PJ_BL 49152
#define PJ_STAGE 81920
#define PJ_SMEM 163840
#define PJ_THREADS 256

__global__ void __launch_bounds__(PJ_THREADS, 1)
proj_tc(const float* __restrict__ bias0, const float* __restrict__ bias1,
        const float* __restrict__ bias2, float* __restrict__ Yout, int base_mode)
{
    extern __shared__ char smem[];
    const uint32_t sbase = smem_to_u32(smem);
    const int tid = threadIdx.x;
    const int wid = tid >> 5;
    const int lane = tid & 31;
    const int wm = wid & 1;
    const int wn = wid >> 1;
    const int m0 = blockIdx.y * 128;
    const int n0 = blockIdx.x * 256;
    const int z = blockIdx.z;
    const int mode = base_mode + z;
    const int wslot = (mode == 3) ? 3 : z;
    const bool twop = (mode == 3);

    const __half* Xh = g_Xh + (size_t)z * XSZ;
    const __half* Wh = g_Wh + (size_t)wslot * WSZ;
    const float* bias = (mode == 3) ? bias0 : ((z == 0) ? bias0 : (z == 1) ? bias1 : bias2);

    float acc[4][8][4];
#pragma unroll
    for (int i = 0; i < 4; i++)
#pragma unroll
        for (int j = 0; j < 8; j++)
#pragma unroll
            for (int k = 0; k < 4; k++) acc[i][j][k] = 0.f;

    const int aRow = wm * 64 + (lane & 15);
    const int aSel = lane >> 4;
    const int bRow = wn * 64 + (lane & 7) + ((lane >> 4) << 3);
    const int bSel = (lane >> 3) & 1;

    auto issue = [&](int c) {
        const uint32_t sb = sbase + (c & 1) * PJ_STAGE;
        const int k0 = c * 64;
#pragma unroll
        for (int t = 0; t < 4; t++) {
            int i = tid + t * PJ_THREADS;
            int r = i >> 3, u = i & 7;
            int sw = r * 128 + ((u ^ (r & 7)) << 4);
            cpasync16(sb + PJ_AH + sw, Xh + (size_t)(m0 + r) * DD + k0 + u * 8);
        }
#pragma unroll
        for (int t = 0; t < 8; t++) {
            int i = tid + t * PJ_THREADS;
            int r = i >> 3, u = i & 7;
            int sw = r * 128 + ((u ^ (r & 7)) << 4);
            size_t gw = (size_t)(n0 + r) * DD + k0 + u * 8;
            cpasync16(sb + PJ_BH + sw, Wh + gw);
            if (twop) cpasync16(sb + PJ_BL + sw, g_Wl + gw);
        }
    };

    issue(0); CP_COMMIT;
    for (int c = 0; c < 16; c++) {
        if (c + 1 < 16) { issue(c + 1); CP_COMMIT; CP_WAITG(1); }
        else CP_WAITG(0);
        __syncthreads();
        const uint32_t sb = sbase + (c & 1) * PJ_STAGE;
#pragma unroll
        for (int ks = 0; ks < 4; ks++) {
            uint32_t bh[4][4], bl[4][4];
#pragma unroll
            for (int p = 0; p < 4; p++) {
                int row = bRow + p * 16;
                uint32_t addr = sb + PJ_BH + (uint32_t)row * 128
                              + (uint32_t)(((ks * 2 + bSel) ^ (row & 7)) << 4);
                ldsm4(bh[p], addr);
                if (twop) ldsm4(bl[p], addr + (PJ_BL - PJ_BH));
            }
#pragma unroll
            for (int mf = 0; mf < 4; mf++) {
                int row = aRow + mf * 16;
                uint32_t addr = sb + (uint32_t)row * 128
                              + (uint32_t)(((ks * 2 + aSel) ^ (row & 7)) << 4);
                uint32_t ah[4];
                ldsm4(ah, addr);
#pragma unroll
                for (int nf = 0; nf < 8; nf++) {
                    const int p = nf >> 1, q = (nf & 1) * 2;
                    mma_fp16(acc[mf][nf], ah, &bh[p][q]);
                    if (twop) mma_fp16(acc[mf][nf], ah, &bl[p][q]);
                }
            }
        }
        __syncthreads();
    }

    // ---- epilogue ----
    if (mode == 3) {
#pragma unroll
        for (int nf = 0; nf < 8; nf++) {
            const int n = n0 + wn * 64 + nf * 8 + (lane & 3) * 2;
            const float bv0 = bias[n], bv1 = bias[n + 1];
#pragma unroll
            for (int mf = 0; mf < 4; mf++) {
                const int m = m0 + wm * 64 + mf * 16 + (lane >> 2);
                float2 v0, v1;
                v0.x = acc[mf][nf][0] + bv0; v0.y = acc[mf][nf][1] + bv1;
                v1.x = acc[mf][nf][2] + bv0; v1.y = acc[mf][nf][3] + bv1;
                *(float2*)&Yout[(size_t)m * DD + n] = v0;
                *(float2*)&Yout[(size_t)(m + 8) * DD + n] = v1;
            }
        }
    } else {
        uint32_t* dst = (mode == 0) ? (uint32_t*)g_Qh
                      : (mode == 1) ? (uint32_t*)g_Kh : (uint32_t*)g_Vh;
        const float qs = (mode == 0) ? 0.18033688011112042f : 1.0f;  // log2(e)/8
#pragma unroll
        for (int nf = 0; nf < 8; nf++) {
            const int n = n0 + wn * 64 + nf * 8 + (lane & 3) * 2;
            const float bv0 = bias[n], bv1 = bias[n + 1];
            const int h = n >> 6, hd = n & 63;
#pragma unroll
            for (int mf = 0; mf < 4; mf++) {
                const int m = m0 + wm * 64 + mf * 16 + (lane >> 2);
                const int b = m >> 11, s = m & 2047;
                uint32_t U0 = cvt2h((acc[mf][nf][0] + bv0) * qs, (acc[mf][nf][1] + bv1) * qs);
                uint32_t U1 = cvt2h((acc[mf][nf][2] + bv0) * qs, (acc[mf][nf][3] + bv1) * qs);
                size_t off = ((size_t)(b * HH + h) * SS + s) * 32 + (hd >> 1);
                dst[off] = U0;
                dst[off + 256] = U1;   // row s+8
            }
        }
    }
}

// ---------------------------------------------------------------------------
// Two-phase HMMA attention, fp16 single-precision Q/K/V (exact w.r.t. stored
// values). CTA = 128 threads (4 warps), 128 q-rows; each warp owns
// 32 q-rows x 64 keys. Phase A: QK row sums. Phase B: identical QK,
// normalize, write P (streaming), O += P V. Zero-fills upper triangle.
// SMEM: Qh 16KB | K 2x8KB | V 2x8KB = 48KB -> 2 CTAs/SM.
// ---------------------------------------------------------------------------
#define AQH 0
#define AK0 16384
#define AV0 32768
#define ATTN_SMEM 49152
#define AT_THREADS 128

__global__ void __launch_bounds__(AT_THREADS, 2) attn_tc(float* __restrict__ d_attn)
{
    extern __shared__ char smem[];
    const uint32_t sbase = smem_to_u32(smem);
    const int bh = blockIdx.x;
    const int qt = (int)gridDim.y - 1 - (int)blockIdx.y;   // big tiles first
    const int tid = threadIdx.x;
    const int wid = tid >> 5;          // 0..3
    const int lane = tid & 31;
    const int g = lane >> 2, t = lane & 3;
    const int qbase = qt * 128;
    const int nkt = 2 * qt + 2;

    // ---- load Qh tile (128 rows x 128B), swizzled ----
    {
        const uint4* srcH = (const uint4*)g_Qh + ((size_t)bh * SS + qbase) * 8;
#pragma unroll
        for (int j = 0; j < 8; j++) {
            int i = tid + j * AT_THREADS;
            int r = i >> 3, u = i & 7;
            int sw = r * 128 + ((u ^ (r & 7)) << 4);
            *(uint4*)(smem + AQH + sw) = srcH[r * 8 + u];
        }
    }

    const int aRowB = wid * 32 + (lane & 15);     // + mf*16
    const int aSel = lane >> 4;
    const int bRowB = (lane & 7) + ((lane >> 4) << 3);
    const int bSel = (lane >> 3) & 1;
    const int vRowB = (lane & 7) + (((lane >> 3) & 1) << 3);
    const int vSel = lane >> 4;

    const int q00 = qbase + wid * 32 + g;
    const int q01 = q00 + 8;
    const int q10 = q00 + 16;
    const int q11 = q00 + 24;

    auto issueK = [&](int kt, int st) {
        size_t rb = ((size_t)bh * SS + kt * 64) * 8;
        uint32_t sb = sbase + AK0 + st * 8192;
#pragma unroll
        for (int j = 0; j < 4; j++) {
            int i = tid + j * AT_THREADS;
            int r = i >> 3, u = i & 7;
            int sw = r * 128 + ((u ^ (r & 7)) << 4);
            cpasync16(sb + sw, (const uint4*)g_Kh + rb + r * 8 + u);
        }
    };
    auto issueV = [&](int kt, int st) {
        size_t rb = ((size_t)bh * SS + kt * 64) * 8;
        uint32_t sb = sbase + AV0 + st * 8192;
#pragma unroll
        for (int j = 0; j < 4; j++) {
            int i = tid + j * AT_THREADS;
            int r = i >> 3, u = i & 7;
            int sw = r * 128 + ((u ^ (r & 7)) << 4);
            cpasync16(sb + sw, (const uint4*)g_Vh + rb + r * 8 + u);
        }
    };

    // S = Q K^T for one stage, both mf (single-pass; exact vs stored fp16)
    auto computeS = [&](int st, float s[2][8][4]) {
        const uint32_t kb = sbase + AK0 + st * 8192;
#pragma unroll
        for (int mf = 0; mf < 2; mf++)
#pragma unroll
            for (int f = 0; f < 8; f++)
#pragma unroll
                for (int k = 0; k < 4; k++) s[mf][f][k] = 0.f;
#pragma unroll
        for (int ks = 0; ks < 4; ks++) {
            uint32_t ah[2][4];
#pragma unroll
            for (int mf = 0; mf < 2; mf++) {
                int row = aRowB + mf * 16;
                uint32_t addrA = sbase + AQH + (uint32_t)row * 128
                               + (uint32_t)((((ks << 1) + aSel) ^ (row & 7)) << 4);
                ldsm4(ah[mf], addrA);
            }
#pragma unroll
            for (int p = 0; p < 4; p++) {
                int row = bRowB + p * 16;
                uint32_t addrB = kb + (uint32_t)row * 128
                               + (uint32_t)((((ks << 1) + bSel) ^ (row & 7)) << 4);
                uint32_t kh[4];
                ldsm4(kh, addrB);
#pragma unroll
                for (int mf = 0; mf < 2; mf++) {
                    mma_fp16(s[mf][2 * p],     ah[mf], &kh[0]);
                    mma_fp16(s[mf][2 * p + 1], ah[mf], &kh[2]);
                }
            }
        }
    };

    // ================= Phase A: row sums =================
    float rs[2][2] = {{0.f, 0.f}, {0.f, 0.f}};
    issueK(0, 0); CP_COMMIT;
    for (int kt = 0; kt < nkt; kt++) {
        if (kt + 1 < nkt) { issueK(kt + 1, (kt + 1) & 1); CP_COMMIT; CP_WAITG(1); }
        else CP_WAITG(0);
        __syncthreads();
        float s[2][8][4];
        computeS(kt & 1, s);
        __syncthreads();   // stage reads done before next overwrite

        const int kcb = kt * 64 + 2 * t;
#pragma unroll
        for (int mf = 0; mf < 2; mf++) {
            const int qa = qbase + wid * 32 + mf * 16;
            const bool full = (kt * 64 + 63) <= qa;
            const int qr0 = qa + g, qr1 = qr0 + 8;
#pragma unroll
            for (int f = 0; f < 8; f++) {
                int kc = kcb + 8 * f;
                float p0 = ex2f(s[mf][f][0]);
                float p1 = ex2f(s[mf][f][1]);
                float p2 = ex2f(s[mf][f][2]);
                float p3 = ex2f(s[mf][f][3]);
                if (!full) {
                    p0 = (kc     <= qr0) ? p0 : 0.f;
                    p1 = (kc + 1 <= qr0) ? p1 : 0.f;
                    p2 = (kc     <= qr1) ? p2 : 0.f;
                    p3 = (kc + 1 <= qr1) ? p3 : 0.f;
                }
                rs[mf][0] += p0 + p1;
                rs[mf][1] += p2 + p3;
            }
        }
    }
#pragma unroll
    for (int mf = 0; mf < 2; mf++)
#pragma unroll
        for (int rr = 0; rr < 2; rr++) {
            rs[mf][rr] += __shfl_xor_sync(0xFFFFFFFFu, rs[mf][rr], 1);
            rs[mf][rr] += __shfl_xor_sync(0xFFFFFFFFu, rs[mf][rr], 2);
        }
    const float inv00 = 1.f / rs[0][0], inv01 = 1.f / rs[0][1];
    const float inv10 = 1.f / rs[1][0], inv11 = 1.f / rs[1][1];

    // ---- zero-fill this CTA's upper-triangle strip (streaming stores) ----
    {
        const int zstart = qbase + 128;
        for (int r = 0; r < 128 && zstart < SS; r++) {
            float* rowp = d_attn + ((size_t)bh * SS + qbase + r) * SS;
            for (int kc = zstart + tid * 4; kc < SS; kc += AT_THREADS * 4)
                stcs4z(&rowp[kc]);
        }
    }

    // ================= Phase B: normalized P store + O accumulate =========
    float o[2][8][4];
#pragma unroll
    for (int mf = 0; mf < 2; mf++)
#pragma unroll
        for (int f = 0; f < 8; f++)
#pragma unroll
            for (int k = 0; k < 4; k++) o[mf][f][k] = 0.f;

    float* attn00 = d_attn + ((size_t)bh * SS + q00) * SS;
    float* attn01 = d_attn + ((size_t)bh * SS + q01) * SS;
    float* attn10 = d_attn + ((size_t)bh * SS + q10) * SS;
    float* attn11 = d_attn + ((size_t)bh * SS + q11) * SS;

    issueK(0, 0); issueV(0, 0); CP_COMMIT;
    for (int kt = 0; kt < nkt; kt++) {
        if (kt + 1 < nkt) {
            issueK(kt + 1, (kt + 1) & 1); issueV(kt + 1, (kt + 1) & 1);
            CP_COMMIT; CP_WAITG(1);
        } else CP_WAITG(0);
        __syncthreads();

        float s[2][8][4];
        computeS(kt & 1, s);

        const int kcb = kt * 64 + 2 * t;
        uint32_t pa[2][4][4];
#pragma unroll
        for (int mf = 0; mf < 2; mf++) {
            const int qa = qbase + wid * 32 + mf * 16;
            const bool full = (kt * 64 + 63) <= qa;
            const int qr0 = qa + g, qr1 = qr0 + 8;
            const float i0 = (mf == 0) ? inv00 : inv10;
            const float i1 = (mf == 0) ? inv01 : inv11;
            float* a0 = (mf == 0) ? attn00 : attn10;
            float* a1 = (mf == 0) ? attn01 : attn11;
#pragma unroll
            for (int f = 0; f < 8; f++) {
                int kc = kcb + 8 * f;
                float p0 = ex2f(s[mf][f][0]) * i0;
                float p1 = ex2f(s[mf][f][1]) * i0;
                float p2 = ex2f(s[mf][f][2]) * i1;
                float p3 = ex2f(s[mf][f][3]) * i1;
                if (!full) {
                    p0 = (kc     <= qr0) ? p0 : 0.f;
                    p1 = (kc + 1 <= qr0) ? p1 : 0.f;
                    p2 = (kc     <= qr1) ? p2 : 0.f;
                    p3 = (kc + 1 <= qr1) ? p3 : 0.f;
                }
                stcs2(&a0[kc], p0, p1);
                stcs2(&a1[kc], p2, p3);
                int ks = f >> 1, o2 = (f & 1) << 1;
                pa[mf][ks][o2]     = cvt2h(p0, p1);
                pa[mf][ks][o2 + 1] = cvt2h(p2, p3);
            }
        }

        // O += P V (single-pass fp16), V from this stage
        const uint32_t vb = sbase + AV0 + (kt & 1) * 8192;
#pragma unroll
        for (int ks = 0; ks < 4; ks++) {
            int row = vRowB + ks * 16;
#pragma unroll
            for (int p = 0; p < 4; p++) {
                int cu = p * 2 + vSel;
                uint32_t addrV = vb + (uint32_t)row * 128
                               + (uint32_t)((cu ^ (row & 7)) << 4);
                uint32_t vh[4];
                ldsm4t(vh, addrV);
#pragma unroll
                for (int mf = 0; mf < 2; mf++) {
                    mma_fp16(o[mf][2 * p],     pa[mf][ks], &vh[0]);
                    mma_fp16(o[mf][2 * p + 1], pa[mf][ks], &vh[2]);
                }
            }
        }
        __syncthreads();   // stage reads done before next overwrite
    }

    // ---- store O as single fp16 into X slot 0 (for out projection) ----
    const int b = bh >> 4, h = bh & 15;
    uint32_t* xh = (uint32_t*)g_Xh;
#pragma unroll
    for (int mf = 0; mf < 2; mf++) {
        const int qr0 = (mf == 0) ? q00 : q10;
        const int qr1 = qr0 + 8;
        const size_t base0 = (((size_t)b * SS + qr0) * DD + h * 64) >> 1;
        const size_t base1 = (((size_t)b * SS + qr1) * DD + h * 64) >> 1;
#pragma unroll
        for (int f = 0; f < 8; f++) {
            int col = 8 * f + 2 * t;       // even
            xh[base0 + (col >> 1)] = cvt2h(o[mf][f][0], o[mf][f][1]);
            xh[base1 + (col >> 1)] = cvt2h(o[mf][f][2], o[mf][f][3]);
        }
    }
}

// ---------------------------------------------------------------------------
extern "C" void kernel_launch(void* const* d_in, const int* in_sizes, int n_in,
                              void* d_out, int out_size)
{
    const float* queries = (const float*)d_in[0];
    const float* keys    = (const float*)d_in[1];
    const float* values  = (const float*)d_in[2];
    // d_in[3] = attn_mask (bool, causal) — applied analytically
    const float* wq = (const float*)d_in[4];
    const float* bq = (const float*)d_in[5];
    const float* wk = (const float*)d_in[6];
    const float* bk = (const float*)d_in[7];
    const float* wv = (const float*)d_in[8];
    const float* bv = (const float*)d_in[9];
    const float* wo = (const float*)d_in[10];
    const float* bo = (const float*)d_in[11];

    float* out   = (float*)d_out;
    float* attnW = out + OUT_ELEMS;

    cudaFuncSetAttribute(proj_tc, cudaFuncAttributeMaxDynamicSharedMemorySize, PJ_SMEM);
    cudaFuncSetAttribute(attn_tc, cudaFuncAttributeMaxDynamicSharedMemorySize, ATTN_SMEM);

    // 1) convert all inputs (one launch, high-MLP)
    cvt_all<<<1024, 256>>>((const float4*)queries, (const float4*)keys,
                           (const float4*)values,  (const float4*)wq,
                           (const float4*)wk, (const float4*)wv, (const float4*)wo);

    // 2) Q/K/V projections in one launch (grid.z = 3), all 1-pass fp16
    dim3 gg(DD / 256, MROWS / 128, 3);   // (4, 32, 3) = 384 CTAs
    proj_tc<<<gg, PJ_THREADS, PJ_SMEM>>>(bq, bk, bv, nullptr, 0);

    // 3) fused attention (single-fp16 Q/K/V, 1-pass QK), 2 CTAs/SM
    dim3 ga(BB * HH, SS / 128);          // (32, 16) = 512 CTAs
    attn_tc<<<ga, AT_THREADS, ATTN_SMEM>>>(attnW);

    // 4) output projection (reads X slot 0 written by attn_tc), fp16 2-pass
    dim3 go(DD / 256, MROWS / 128, 1);   // (4, 32) = 128 CTAs
    proj_tc<<<go, PJ_THREADS, PJ_SMEM>>>(bo, nullptr, nullptr, out, 3);
}